// round 15
// baseline (speedup 1.0000x reference)
#include <cuda_runtime.h>
#include <cuda_fp16.h>
#include <math.h>
#include <stdint.h>

// Problem dims
#define BB 8
#define SS 16
#define HH 32
#define WW 32
#define EE 128
#define NTOK (BB*SS*HH*WW)      // 131072
#define NPIX (BB*HH*WW)          // 8192

// conv planar layout (half2 words): [chunk][j8][34 rows][36 cols]
#define JPL   1224               // 34*36 half2 per j-plane
#define CHW   9792               // 8*JPL per chunk (16 ic)
#define SBW   78336              // 8 chunks per (s,b) x-part
#define AST   68                 // half2-word stride for GEMM A/B tiles

// ---------------- scratch (device globals) ----------------------------------
__device__ __align__(16) uint32_t g_qkvh[NTOK*192];   // qkv fp16 (100 MB)
__device__ __align__(16) uint32_t g_aoh [NTOK*64];    // attn out fp16 (33 MB)
__device__ __align__(16) uint32_t g_padx[SS*BB*SBW];  // 40 MB: x, all steps
__device__ __align__(16) uint32_t g_padh[2*BB*SBW];   // h, ping-pong
__device__ __align__(16) uint32_t g_w2h [16*9*8*512]; // [chunk16][tap9][j8][oc'512]
__device__ unsigned g_bar;                            // grid barrier counter

__device__ __forceinline__ uint32_t sm_u32(const void* p) {
    return (uint32_t)__cvta_generic_to_shared(p);
}
__device__ __forceinline__ void cpa16(uint32_t dst, const void* src) {
    asm volatile("cp.async.cg.shared.global [%0], [%1], 16;\n" :: "r"(dst), "l"(src));
}
__device__ __forceinline__ uint32_t pack_h2(float a, float b) {
    __half2 h = __halves2half2(__float2half_rn(a), __float2half_rn(b));
    return *(uint32_t*)&h;
}
__device__ __forceinline__ float2 unpack_h2(uint32_t u) {
    __half2 h = *(__half2*)&u;
    return __half22float2(h);
}

#define MMA_F16(acc, af, bf)                                               \
    asm volatile(                                                          \
        "mma.sync.aligned.m16n8k16.row.col.f32.f16.f16.f32 "               \
        "{%0,%1,%2,%3}, {%4,%5,%6,%7}, {%8,%9}, {%0,%1,%2,%3};"            \
        : "+f"(acc[0]), "+f"(acc[1]), "+f"(acc[2]), "+f"(acc[3])           \
        : "r"(af[0]), "r"(af[1]), "r"(af[2]), "r"(af[3]),                  \
          "r"(bf[0]), "r"(bf[1]))

// ---------------- fused front: silu(in@Wp) -> LN -> @W_in -> g_qkvh ---------
__global__ void __launch_bounds__(256) front_fused_kernel(
    const float* __restrict__ inputs, const float* __restrict__ Wp,
    const float* __restrict__ Win,
    const float* __restrict__ gamma, const float* __restrict__ beta)
{
    extern __shared__ uint32_t fsm[];
    uint32_t* Ah = fsm;            // R1
    uint32_t* Bh = fsm + 8704;     // R2
    uint32_t* Xh = fsm + 17408;    // R3
    float*    Xs = (float*)fsm;    // alias R1+R2: 128 x 132 fp32

    const int m0 = blockIdx.x * 128;
    const int t = threadIdx.x, lane = t & 31, warp = t >> 5;
    const int wm = warp & 3, wn = warp >> 2;

    #pragma unroll
    for (int j = 0; j < 16; j++) {
        int idx = t + j * 256;
        int row = idx >> 5, c4 = idx & 31;
        float4 v = *(const float4*)&inputs[(m0 + row) * 128 + c4 * 4];
        Ah[row * AST + c4 * 2]     = pack_h2(v.x, v.y);
        Ah[row * AST + c4 * 2 + 1] = pack_h2(v.z, v.w);
    }
    #pragma unroll
    for (int i = 0; i < 32; i++) {
        int idx = t + i * 256;
        int n = idx & 127, kp = idx >> 7;
        Bh[n * AST + kp] = pack_h2(Wp[(2 * kp) * 128 + n], Wp[(2 * kp + 1) * 128 + n]);
    }
    __syncthreads();

    float acc[2][8][4] = {};
    #pragma unroll
    for (int st = 0; st < 8; st++) {
        uint32_t af[2][4], bf[8][2];
        #pragma unroll
        for (int mi = 0; mi < 2; mi++) {
            int base = (wm * 32 + mi * 16 + (lane >> 2)) * AST + st * 8 + (lane & 3);
            af[mi][0] = Ah[base];
            af[mi][1] = Ah[base + 8 * AST];
            af[mi][2] = Ah[base + 4];
            af[mi][3] = Ah[base + 8 * AST + 4];
        }
        #pragma unroll
        for (int ni = 0; ni < 8; ni++) {
            int b = (wn * 64 + ni * 8 + (lane >> 2)) * AST + st * 8 + (lane & 3);
            bf[ni][0] = Bh[b];
            bf[ni][1] = Bh[b + 4];
        }
        #pragma unroll
        for (int mi = 0; mi < 2; mi++)
            #pragma unroll
            for (int ni = 0; ni < 8; ni++)
                MMA_F16(acc[mi][ni], af[mi], bf[ni]);
    }
    __syncthreads();

    #pragma unroll
    for (int mi = 0; mi < 2; mi++)
        #pragma unroll
        for (int ni = 0; ni < 8; ni++) {
            int r = wm * 32 + mi * 16 + (lane >> 2);
            int cc = wn * 64 + ni * 8 + 2 * (lane & 3);
            float2 v0 = {acc[mi][ni][0], acc[mi][ni][1]};
            float2 v1 = {acc[mi][ni][2], acc[mi][ni][3]};
            v0.x = v0.x / (1.0f + expf(-v0.x)); v0.y = v0.y / (1.0f + expf(-v0.y));
            v1.x = v1.x / (1.0f + expf(-v1.x)); v1.y = v1.y / (1.0f + expf(-v1.y));
            *(float2*)&Xs[r * 132 + cc]       = v0;
            *(float2*)&Xs[(r + 8) * 132 + cc] = v1;
        }
    __syncthreads();

    {
        float4 g4 = *(const float4*)&gamma[lane * 4];
        float4 b4 = *(const float4*)&beta [lane * 4];
        for (int rl = 0; rl < 16; rl++) {
            int row = warp * 16 + rl;
            float4 v = *(float4*)&Xs[row * 132 + lane * 4];
            float s = v.x + v.y + v.z + v.w;
            float q = v.x * v.x + v.y * v.y + v.z * v.z + v.w * v.w;
            #pragma unroll
            for (int off = 16; off > 0; off >>= 1) {
                s += __shfl_xor_sync(0xFFFFFFFF, s, off);
                q += __shfl_xor_sync(0xFFFFFFFF, q, off);
            }
            float mu  = s * (1.0f / 128.0f);
            float var = q * (1.0f / 128.0f) - mu * mu;
            float rs  = rsqrtf(var + 1e-5f);
            float nx = (v.x - mu) * rs * g4.x + b4.x;
            float ny = (v.y - mu) * rs * g4.y + b4.y;
            float nz = (v.z - mu) * rs * g4.z + b4.z;
            float nw = (v.w - mu) * rs * g4.w + b4.w;
            Xh[row * AST + lane * 2]     = pack_h2(nx, ny);
            Xh[row * AST + lane * 2 + 1] = pack_h2(nz, nw);
        }
    }
    __syncthreads();

    for (int nt = 0; nt < 3; nt++) {
        #pragma unroll
        for (int i = 0; i < 32; i++) {
            int idx = t + i * 256;
            int n = idx & 127, kp = idx >> 7;
            Bh[n * AST + kp] = pack_h2(Win[(2 * kp) * 384 + nt * 128 + n],
                                       Win[(2 * kp + 1) * 384 + nt * 128 + n]);
        }
        __syncthreads();

        float a2[2][8][4] = {};
        #pragma unroll
        for (int st = 0; st < 8; st++) {
            uint32_t af[2][4], bf[8][2];
            #pragma unroll
            for (int mi = 0; mi < 2; mi++) {
                int base = (wm * 32 + mi * 16 + (lane >> 2)) * AST + st * 8 + (lane & 3);
                af[mi][0] = Xh[base];
                af[mi][1] = Xh[base + 8 * AST];
                af[mi][2] = Xh[base + 4];
                af[mi][3] = Xh[base + 8 * AST + 4];
            }
            #pragma unroll
            for (int ni = 0; ni < 8; ni++) {
                int b = (wn * 64 + ni * 8 + (lane >> 2)) * AST + st * 8 + (lane & 3);
                bf[ni][0] = Bh[b];
                bf[ni][1] = Bh[b + 4];
            }
            #pragma unroll
            for (int mi = 0; mi < 2; mi++)
                #pragma unroll
                for (int ni = 0; ni < 8; ni++)
                    MMA_F16(a2[mi][ni], af[mi], bf[ni]);
        }

        #pragma unroll
        for (int mi = 0; mi < 2; mi++)
            #pragma unroll
            for (int ni = 0; ni < 8; ni++) {
                int r0 = m0 + wm * 32 + mi * 16 + (lane >> 2);
                int cc = wn * 64 + ni * 8 + 2 * (lane & 3);
                int wcol = nt * 64 + (cc >> 1);
                g_qkvh[r0 * 192 + wcol]       = pack_h2(a2[mi][ni][0], a2[mi][ni][1]);
                g_qkvh[(r0 + 8) * 192 + wcol] = pack_h2(a2[mi][ni][2], a2[mi][ni][3]);
            }
        __syncthreads();
    }
}

// ---------------- Attention: fp16 qkv in, fp32 smem compute, fp16 ao out ----
__global__ void __launch_bounds__(256) attn_kernel2()
{
    extern __shared__ float qs[];          // 32 rows x stride 388 (fp32)
    const int bid = blockIdx.x;
    const int wp = bid & 15;
    const int h  = (bid >> 4) & 31;
    const int b  = bid >> 9;
    const int w0 = wp * 2;
    const int t  = threadIdx.x;

    #pragma unroll
    for (int j = 0; j < 24; j++) {
        int idx = t + j * 256;
        int ti = idx / 192, w = idx % 192;
        int s_ = ti >> 1, wl = ti & 1;
        uint32_t u = g_qkvh[(((b * 16 + s_) * 1024) + h * 32 + w0 + wl) * 192 + w];
        float2 f = unpack_h2(u);
        *(float2*)&qs[ti * 388 + 2 * w] = f;
    }
    __syncthreads();

    const int gl = t >> 4, sq = t & 15;
    const int nh = gl & 7, wl = gl >> 3;
    const int ti_q = sq * 2 + wl;
    const float* qrow = &qs[ti_q * 388 + nh * 48];
    float q[16];
    #pragma unroll
    for (int d = 0; d < 16; d++) q[d] = qrow[d];

    float sc[16];
    float mx = -1e30f;
    #pragma unroll
    for (int l = 0; l < 16; l++) {
        const float* krow = &qs[(l * 2 + wl) * 388 + nh * 48 + 16];
        float d = 0.0f;
        #pragma unroll
        for (int dd = 0; dd < 16; dd++) d += q[dd] * krow[dd];
        float m = (l <= sq) ? 1.0f : -1000.0f;
        sc[l] = d * 0.25f + m;
        mx = fmaxf(mx, sc[l]);
    }
    float sum = 0.0f;
    #pragma unroll
    for (int l = 0; l < 16; l++) { sc[l] = expf(sc[l] - mx); sum += sc[l]; }
    float inv = 1.0f / sum;

    float o[16] = {};
    #pragma unroll
    for (int l = 0; l < 16; l++) {
        float pl = sc[l] * inv;
        const float* vrow = &qs[(l * 2 + wl) * 388 + nh * 48 + 32];
        #pragma unroll
        for (int dd = 0; dd < 16; dd++) o[dd] += pl * vrow[dd];
    }
    __syncthreads();
    #pragma unroll
    for (int d = 0; d < 16; d++) qs[ti_q * 388 + nh * 16 + d] = o[d];
    __syncthreads();

    #pragma unroll
    for (int j = 0; j < 8; j++) {
        int idx = t + j * 256;
        int ti = idx >> 6, w = idx & 63;
        int s_ = ti >> 1, wl2 = ti & 1;
        g_aoh[(((b * 16 + s_) * 1024) + h * 32 + w0 + wl2) * 64 + w]
            = pack_h2(qs[ti * 388 + 2 * w], qs[ti * 388 + 2 * w + 1]);
    }
}

// ---------------- out GEMM (fp16) + residual + pack into g_padx -------------
__global__ void __launch_bounds__(256) gemm_out_pack_kernel(
    const float* __restrict__ Wout, const float* __restrict__ inputs)
{
    extern __shared__ uint32_t osm[];
    uint32_t* Ah = osm;            // 128 x AST
    uint32_t* Bh = osm + 8704;

    const int m0 = blockIdx.x * 128;
    const int t = threadIdx.x, lane = t & 31, warp = t >> 5;
    const int wm = warp & 3, wn = warp >> 2;

    #pragma unroll
    for (int i = 0; i < 8; i++) {
        int idx = t + i * 256;
        int row = idx >> 4, q4 = idx & 15;
        *(uint4*)&Ah[row * AST + q4 * 4] = *(const uint4*)&g_aoh[(m0 + row) * 64 + q4 * 4];
    }
    #pragma unroll
    for (int i = 0; i < 32; i++) {
        int idx = t + i * 256;
        int n = idx & 127, kp = idx >> 7;
        Bh[n * AST + kp] = pack_h2(Wout[(2 * kp) * 128 + n], Wout[(2 * kp + 1) * 128 + n]);
    }
    __syncthreads();

    float acc[2][8][4] = {};
    #pragma unroll
    for (int st = 0; st < 8; st++) {
        uint32_t af[2][4], bf[8][2];
        #pragma unroll
        for (int mi = 0; mi < 2; mi++) {
            int base = (wm * 32 + mi * 16 + (lane >> 2)) * AST + st * 8 + (lane & 3);
            af[mi][0] = Ah[base];
            af[mi][1] = Ah[base + 8 * AST];
            af[mi][2] = Ah[base + 4];
            af[mi][3] = Ah[base + 8 * AST + 4];
        }
        #pragma unroll
        for (int ni = 0; ni < 8; ni++) {
            int b = (wn * 64 + ni * 8 + (lane >> 2)) * AST + st * 8 + (lane & 3);
            bf[ni][0] = Bh[b];
            bf[ni][1] = Bh[b + 4];
        }
        #pragma unroll
        for (int mi = 0; mi < 2; mi++)
            #pragma unroll
            for (int ni = 0; ni < 8; ni++)
                MMA_F16(acc[mi][ni], af[mi], bf[ni]);
    }

    #pragma unroll
    for (int mi = 0; mi < 2; mi++)
        #pragma unroll
        for (int ni = 0; ni < 8; ni++) {
            int cc = wn * 64 + ni * 8 + 2 * (lane & 3);     // even e
            int chunk = cc >> 4, jp = (cc & 15) >> 1;
            #pragma unroll
            for (int half = 0; half < 2; half++) {
                int r = m0 + wm * 32 + mi * 16 + (lane >> 2) + half * 8;
                float2 rv = *(const float2*)&inputs[r * 128 + cc];
                float vx = acc[mi][ni][half * 2 + 0] + rv.x;
                float vy = acc[mi][ni][half * 2 + 1] + rv.y;
                int b_ = r >> 14, s_ = (r >> 10) & 15, y = (r >> 5) & 31, x = r & 31;
                g_padx[(s_ * 8 + b_) * SBW + (chunk * 8 + jp) * JPL + (y + 1) * 36 + (x + 1)]
                    = pack_h2(vx, vy);
            }
        }
}

// ---------------- init: zero padh buf0 + barrier counter --------------------
__global__ void zero_init_kernel()
{
    int idx = blockIdx.x * 256 + threadIdx.x;   // BB*SBW = 626,688 exact
    g_padh[idx] = 0u;
    if (idx == 0) g_bar = 0u;
}
// weights: convk[oc][ic][tap] -> g_w2h[chunk16][tap9][j8][oc'512] half2 (ic0, ic0+1)
// oc' = eg*128 + gate*32 + el  <->  oc_orig = gate*128 + eg*32 + el
__global__ void wprep_kernel(const float* __restrict__ convk)
{
    int idx = blockIdx.x * 256 + threadIdx.x;   // 589,824 exact
    int ocp = idx & 511;
    int t2 = idx >> 9;
    int j  = t2 & 7;
    int t3 = t2 >> 3;
    int tap = t3 % 9;
    int chunk = t3 / 9;
    int eg   = ocp >> 7;
    int gate = (ocp >> 5) & 3;
    int el   = ocp & 31;
    int oc   = gate * 128 + eg * 32 + el;
    int ic0  = chunk * 16 + 2 * j;
    g_w2h[idx] = pack_h2(convk[(oc * 256 + ic0) * 9 + tap],
                         convk[(oc * 256 + ic0 + 1) * 9 + tap]);
}

// ---------------- PERSISTENT ConvLSTM scan ----------------------------------
// Grid 256 (all co-resident at 2 blocks/SM), whole 16-step scan in ONE kernel.
// c-state lives in smem (block tile is fixed across steps). Manual grid
// barrier between x-chunks (0-7) and h-chunks (8-15) -> x-MMA overlaps waiting.
__global__ void __launch_bounds__(256, 2) conv_persist_kernel(float* __restrict__ out)
{
    extern __shared__ uint32_t sh[];
    uint32_t* in_base = sh;                 // 2 x 1728
    uint32_t* w_base  = sh + 2 * 1728;      // 2 x 9792
    float*    Cs      = (float*)sh;         // epilogue alias: 128 x 132 (67.5 KB)
    float*    cst     = (float*)(sh + 23040);  // c-state: 4096 floats (16 KB)

    const int bx  = blockIdx.x;
    const int eg  = bx & 3;
    const int y0  = ((bx >> 2) & 7) * 4;
    const int b   = bx >> 5;
    const int t    = threadIdx.x;
    const int lane = t & 31;
    const int warp = t >> 5;
    const int wm = warp & 3, wn = warp >> 2;
    const int jl = lane & 3, nl = lane >> 2;

    const uint32_t sm_in = sm_u32(in_base);
    const uint32_t sm_w  = sm_u32(w_base);

    // zero block-private c-state
    #pragma unroll
    for (int i = 0; i < 16; i++) cst[i * 256 + t] = 0.0f;

    volatile unsigned* barp = &g_bar;

    for (int s = 0; s < SS; s++) {
        const uint32_t* padx_b = g_padx + (s * 8 + b) * SBW;
        const uint32_t* padh_r = g_padh + (s & 1) * (BB * SBW) + b * SBW;
        uint32_t*       padh_w = g_padh + ((s + 1) & 1) * (BB * SBW);

        auto load_chunk = [&](int stage, int c) {
            const uint32_t* ibase = (c < 8) ? (padx_b + c * CHW) : (padh_r + (c - 8) * CHW);
            uint32_t id = sm_in + (uint32_t)stage * 1728u * 4u;
            #pragma unroll
            for (int k = 0; k < 2; k++) {
                int idx = t + k * 256;
                if (idx < 432) {
                    int j = idx / 54, rem = idx % 54;
                    int r = rem / 9, c16 = rem % 9;
                    cpa16(id + (uint32_t)(j * 216 + r * 36 + c16 * 4) * 4u,
                          ibase + j * JPL + (y0 + r) * 36 + c16 * 4);
                }
            }
            uint32_t wd = sm_w + (uint32_t)stage * 9792u * 4u;
            const uint32_t* wbase = g_w2h + c * 36864 + eg * 128;
            #pragma unroll
            for (int k = 0; k < 9; k++) {
                int idx = t + k * 256;
                int row = idx >> 5, c16 = idx & 31;
                cpa16(wd + (uint32_t)(row * 136 + c16 * 4) * 4u,
                      wbase + row * 512 + c16 * 4);
            }
            asm volatile("cp.async.commit_group;\n");
        };

        float acc[2][8][4] = {};
        load_chunk(0, 0);

        for (int c = 0; c < 16; c++) {
            const int stage = c & 1;
            if (c < 15) {
                if (c == 7) {
                    // grid barrier: h[s-1] must be fully written before chunk 8 load.
                    // x-chunk MMAs above overlap other blocks' step-(s-1) epilogues.
                    __syncthreads();
                    if (t == 0) {
                        unsigned tgt = 256u * (unsigned)s;
                        while (*barp < tgt) {}
                    }
                    __syncthreads();
                }
                load_chunk(stage ^ 1, c + 1);
                asm volatile("cp.async.wait_group 1;\n");
            } else {
                asm volatile("cp.async.wait_group 0;\n");
            }
            __syncthreads();

            const uint32_t* in_s = in_base + stage * 1728;
            const uint32_t* w_s  = w_base  + stage * 9792;

            #pragma unroll
            for (int tp = 0; tp < 9; tp++) {
                const int ky = tp / 3, kx = tp % 3;
                uint32_t bf[8][2];
                #pragma unroll
                for (int g = 0; g < 8; g++) {
                    int ocl = wn * 64 + g * 8 + nl;
                    bf[g][0] = w_s[(tp * 8 + jl    ) * 136 + ocl];
                    bf[g][1] = w_s[(tp * 8 + jl + 4) * 136 + ocl];
                }
                const int rr = wm + ky;
                #pragma unroll
                for (int f = 0; f < 2; f++) {
                    int col = f * 16 + nl + kx;
                    const uint32_t* p0 = in_s + jl * 216 + rr * 36 + col;
                    const uint32_t* p1 = in_s + (jl + 4) * 216 + rr * 36 + col;
                    uint32_t a0 = p0[0], a1 = p0[8], a2 = p1[0], a3 = p1[8];
                    #pragma unroll
                    for (int g = 0; g < 8; g++) {
                        asm volatile(
                            "mma.sync.aligned.m16n8k16.row.col.f32.f16.f16.f32 "
                            "{%0,%1,%2,%3}, {%4,%5,%6,%7}, {%8,%9}, {%0,%1,%2,%3};"
                            : "+f"(acc[f][g][0]), "+f"(acc[f][g][1]),
                              "+f"(acc[f][g][2]), "+f"(acc[f][g][3])
                            : "r"(a0), "r"(a1), "r"(a2), "r"(a3),
                              "r"(bf[g][0]), "r"(bf[g][1]));
                    }
                }
            }
            __syncthreads();
        }

        // ---- epilogue: stage C tile in smem (aliases pipeline buffers) ----
        #pragma unroll
        for (int f = 0; f < 2; f++) {
            #pragma unroll
            for (int g = 0; g < 8; g++) {
                int mloc = wm * 32 + f * 16 + nl;
                int ocl  = wn * 64 + g * 8 + 2 * (lane & 3);
                *(float2*)&Cs[mloc * 132 + ocl]       = make_float2(acc[f][g][0], acc[f][g][1]);
                *(float2*)&Cs[(mloc + 8) * 132 + ocl] = make_float2(acc[f][g][2], acc[f][g][3]);
            }
        }
        __syncthreads();

        // ---- gates: c-state in smem; write out + planar fp16 h ----
        __half* padh_h = (__half*)padh_w;
        #pragma unroll
        for (int i = 0; i < 16; i++) {
            int q  = i * 256 + t;              // 0..4095
            int el = q & 31, px = q >> 5;
            int row = px >> 5, x = px & 31;
            int y = y0 + row;
            float ci = Cs[px * 132 + el];
            float cf = Cs[px * 132 + 32 + el];
            float co = Cs[px * 132 + 64 + el];
            float cg = Cs[px * 132 + 96 + el];
            int e  = eg * 32 + el;
            float c  = cst[q];
            float si = 1.0f / (1.0f + expf(-ci));
            float sf = 1.0f / (1.0f + expf(-cf));
            float so = 1.0f / (1.0f + expf(-co));
            float cn = sf * c + si * tanhf(cg);
            float hn = so * tanhf(cn);
            cst[q] = cn;
            out[((b * 16 + s) * 1024 + y * 32 + x) * 128 + e] = hn;
            int chunk_h = e >> 4, j = (e & 15) >> 1, pos = e & 1;
            padh_h[((((b * 8 + chunk_h) * CHW) + j * JPL + (y + 1) * 36 + (x + 1)) << 1) | pos]
                = __float2half_rn(hn);
        }
        __threadfence();
        __syncthreads();         // all h stores fenced + Cs reads done before arrive/reuse
        if (t == 0) atomicAdd(&g_bar, 1u);
    }
}

// ---------------- launch ----------------------------------------------------
extern "C" void kernel_launch(void* const* d_in, const int* in_sizes, int n_in,
                              void* d_out, int out_size)
{
    const float* inputs = (const float*)d_in[0];
    const float* W_proj = (const float*)d_in[1];
    const float* gamma  = (const float*)d_in[2];
    const float* beta   = (const float*)d_in[3];
    const float* W_in   = (const float*)d_in[4];
    const float* W_out  = (const float*)d_in[5];
    const float* convk  = (const float*)d_in[6];
    float* out = (float*)d_out;

    const int FRONT_SMEM = 26112 * 4;                     // 104448
    const int OUT_SMEM   = 17408 * 4;                     // 69632
    const int ATTN_SMEM  = 32 * 388 * 4;                  // 49664
    const int CONVP_SMEM = (2 * 1728 + 2 * 9792 + 4096) * 4; // 108544
    cudaFuncSetAttribute(front_fused_kernel, cudaFuncAttributeMaxDynamicSharedMemorySize, FRONT_SMEM);
    cudaFuncSetAttribute(gemm_out_pack_kernel, cudaFuncAttributeMaxDynamicSharedMemorySize, OUT_SMEM);
    cudaFuncSetAttribute(attn_kernel2, cudaFuncAttributeMaxDynamicSharedMemorySize, ATTN_SMEM);
    cudaFuncSetAttribute(conv_persist_kernel, cudaFuncAttributeMaxDynamicSharedMemorySize, CONVP_SMEM);

    // 1) fused: silu(inputs@W_proj) -> LN -> @W_in -> g_qkvh (fp16)
    front_fused_kernel<<<NTOK / 128, 256, FRONT_SMEM>>>(inputs, W_proj, W_in, gamma, beta);
    // 2) attention (fp16 in/out, fp32 compute)
    attn_kernel2<<<BB * HH * (WW / 2), 256, ATTN_SMEM>>>();
    // 3) out GEMM + residual, packed straight into g_padx
    gemm_out_pack_kernel<<<NTOK / 128, 256, OUT_SMEM>>>(W_out, inputs);
    // 4) init: zero padh buf0 + barrier; pack weights
    zero_init_kernel<<<(BB * SBW) / 256, 256>>>();
    wprep_kernel<<<(16 * 9 * 8 * 512) / 256, 256>>>(convk);
    // 5) ConvLSTM scan: ONE persistent kernel, all 16 steps
    conv_persist_kernel<<<256, 256, CONVP_SMEM>>>(out);
}

// round 16
// speedup vs baseline: 1.0206x; 1.0206x over previous
#include <cuda_runtime.h>
#include <cuda_fp16.h>
#include <math.h>
#include <stdint.h>

// Problem dims
#define BB 8
#define SS 16
#define HH 32
#define WW 32
#define EE 128
#define NTOK (BB*SS*HH*WW)      // 131072
#define NPIX (BB*HH*WW)          // 8192

// conv planar layout (half2 words): [chunk][j8][34 rows][36 cols]
#define JPL   1224               // 34*36 half2 per j-plane
#define CHW   9792               // 8*JPL per chunk (16 ic)
#define SBW   78336              // 8 chunks per (s,b) x-part
#define AST   68                 // half2-word stride for GEMM A/B tiles

// ---------------- scratch (device globals) ----------------------------------
__device__ __align__(16) uint32_t g_qkvh[NTOK*192];   // qkv fp16
__device__ __align__(16) uint32_t g_aoh [NTOK*64];    // attn out fp16
__device__ float g_c  [NPIX*EE];
__device__ __align__(16) uint32_t g_padx[SS*BB*SBW];  // 40 MB: x, all steps
__device__ __align__(16) uint32_t g_padh[2*BB*SBW];   // h, ping-pong
__device__ __align__(16) uint32_t g_w2h [16*9*8*512]; // [chunk16][tap9][j8][oc'512]

__device__ __forceinline__ uint32_t sm_u32(const void* p) {
    return (uint32_t)__cvta_generic_to_shared(p);
}
__device__ __forceinline__ void cpa16(uint32_t dst, const void* src) {
    asm volatile("cp.async.cg.shared.global [%0], [%1], 16;\n" :: "r"(dst), "l"(src));
}
__device__ __forceinline__ uint32_t pack_h2(float a, float b) {
    __half2 h = __halves2half2(__float2half_rn(a), __float2half_rn(b));
    return *(uint32_t*)&h;
}
__device__ __forceinline__ float2 unpack_h2(uint32_t u) {
    __half2 h = *(__half2*)&u;
    return __half22float2(h);
}

#define MMA_F16(acc, af, bf)                                               \
    asm volatile(                                                          \
        "mma.sync.aligned.m16n8k16.row.col.f32.f16.f16.f32 "               \
        "{%0,%1,%2,%3}, {%4,%5,%6,%7}, {%8,%9}, {%0,%1,%2,%3};"            \
        : "+f"(acc[0]), "+f"(acc[1]), "+f"(acc[2]), "+f"(acc[3])           \
        : "r"(af[0]), "r"(af[1]), "r"(af[2]), "r"(af[3]),                  \
          "r"(bf[0]), "r"(bf[1]))

// ---------------- fused front: silu(in@Wp) -> LN(in place, fp16) -> @W_in ---
// smem = Ah(8704) + Bh(8704) = 69.6 KB -> 3 blocks/SM (was 104 KB / 2).
// A tile is dead after GEMM1; silu result packed fp16 straight back into Ah,
// LN runs in place on the fp16 rows (fp32 stats), GEMM2 streams B tiles.
__global__ void __launch_bounds__(256) front_fused_kernel(
    const float* __restrict__ inputs, const float* __restrict__ Wp,
    const float* __restrict__ Win,
    const float* __restrict__ gamma, const float* __restrict__ beta)
{
    extern __shared__ uint32_t fsm[];
    uint32_t* Ah = fsm;            // A tile, then LN'd x (fp16 pairs)
    uint32_t* Bh = fsm + 8704;     // B tiles

    const int m0 = blockIdx.x * 128;
    const int t = threadIdx.x, lane = t & 31, warp = t >> 5;
    const int wm = warp & 3, wn = warp >> 2;

    #pragma unroll
    for (int j = 0; j < 16; j++) {
        int idx = t + j * 256;
        int row = idx >> 5, c4 = idx & 31;
        float4 v = *(const float4*)&inputs[(m0 + row) * 128 + c4 * 4];
        Ah[row * AST + c4 * 2]     = pack_h2(v.x, v.y);
        Ah[row * AST + c4 * 2 + 1] = pack_h2(v.z, v.w);
    }
    #pragma unroll
    for (int i = 0; i < 32; i++) {
        int idx = t + i * 256;
        int n = idx & 127, kp = idx >> 7;
        Bh[n * AST + kp] = pack_h2(Wp[(2 * kp) * 128 + n], Wp[(2 * kp + 1) * 128 + n]);
    }
    __syncthreads();

    // GEMM 1: x = inputs @ W_proj
    float acc[2][8][4] = {};
    #pragma unroll
    for (int st = 0; st < 8; st++) {
        uint32_t af[2][4], bf[8][2];
        #pragma unroll
        for (int mi = 0; mi < 2; mi++) {
            int base = (wm * 32 + mi * 16 + (lane >> 2)) * AST + st * 8 + (lane & 3);
            af[mi][0] = Ah[base];
            af[mi][1] = Ah[base + 8 * AST];
            af[mi][2] = Ah[base + 4];
            af[mi][3] = Ah[base + 8 * AST + 4];
        }
        #pragma unroll
        for (int ni = 0; ni < 8; ni++) {
            int b = (wn * 64 + ni * 8 + (lane >> 2)) * AST + st * 8 + (lane & 3);
            bf[ni][0] = Bh[b];
            bf[ni][1] = Bh[b + 4];
        }
        #pragma unroll
        for (int mi = 0; mi < 2; mi++)
            #pragma unroll
            for (int ni = 0; ni < 8; ni++)
                MMA_F16(acc[mi][ni], af[mi], bf[ni]);
    }
    __syncthreads();   // A reads done before overwrite

    // silu -> pack fp16 directly back into Ah (A tile dead)
    #pragma unroll
    for (int mi = 0; mi < 2; mi++)
        #pragma unroll
        for (int ni = 0; ni < 8; ni++) {
            int r = wm * 32 + mi * 16 + (lane >> 2);
            int w = wn * 32 + ni * 4 + (lane & 3);   // half2 word index (col/2)
            float2 v0 = {acc[mi][ni][0], acc[mi][ni][1]};
            float2 v1 = {acc[mi][ni][2], acc[mi][ni][3]};
            v0.x = v0.x / (1.0f + expf(-v0.x)); v0.y = v0.y / (1.0f + expf(-v0.y));
            v1.x = v1.x / (1.0f + expf(-v1.x)); v1.y = v1.y / (1.0f + expf(-v1.y));
            Ah[r * AST + w]       = pack_h2(v0.x, v0.y);
            Ah[(r + 8) * AST + w] = pack_h2(v1.x, v1.y);
        }
    __syncthreads();

    // LayerNorm in place on Ah rows (fp32 stats; warp w: rows w*16..w*16+15)
    {
        float4 g4 = *(const float4*)&gamma[lane * 4];
        float4 b4 = *(const float4*)&beta [lane * 4];
        for (int rl = 0; rl < 16; rl++) {
            int row = warp * 16 + rl;
            uint32_t u0 = Ah[row * AST + lane * 2];
            uint32_t u1 = Ah[row * AST + lane * 2 + 1];
            float2 a = unpack_h2(u0), b = unpack_h2(u1);
            float s = a.x + a.y + b.x + b.y;
            float q = a.x * a.x + a.y * a.y + b.x * b.x + b.y * b.y;
            #pragma unroll
            for (int off = 16; off > 0; off >>= 1) {
                s += __shfl_xor_sync(0xFFFFFFFF, s, off);
                q += __shfl_xor_sync(0xFFFFFFFF, q, off);
            }
            float mu  = s * (1.0f / 128.0f);
            float var = q * (1.0f / 128.0f) - mu * mu;
            float rs  = rsqrtf(var + 1e-5f);
            float nx = (a.x - mu) * rs * g4.x + b4.x;
            float ny = (a.y - mu) * rs * g4.y + b4.y;
            float nz = (b.x - mu) * rs * g4.z + b4.z;
            float nw = (b.y - mu) * rs * g4.w + b4.w;
            Ah[row * AST + lane * 2]     = pack_h2(nx, ny);
            Ah[row * AST + lane * 2 + 1] = pack_h2(nz, nw);
        }
    }
    __syncthreads();

    // GEMM 2: qkv = x @ W_in, 3 column tiles through Bh
    for (int nt = 0; nt < 3; nt++) {
        #pragma unroll
        for (int i = 0; i < 32; i++) {
            int idx = t + i * 256;
            int n = idx & 127, kp = idx >> 7;
            Bh[n * AST + kp] = pack_h2(Win[(2 * kp) * 384 + nt * 128 + n],
                                       Win[(2 * kp + 1) * 384 + nt * 128 + n]);
        }
        __syncthreads();

        float a2[2][8][4] = {};
        #pragma unroll
        for (int st = 0; st < 8; st++) {
            uint32_t af[2][4], bf[8][2];
            #pragma unroll
            for (int mi = 0; mi < 2; mi++) {
                int base = (wm * 32 + mi * 16 + (lane >> 2)) * AST + st * 8 + (lane & 3);
                af[mi][0] = Ah[base];
                af[mi][1] = Ah[base + 8 * AST];
                af[mi][2] = Ah[base + 4];
                af[mi][3] = Ah[base + 8 * AST + 4];
            }
            #pragma unroll
            for (int ni = 0; ni < 8; ni++) {
                int b = (wn * 64 + ni * 8 + (lane >> 2)) * AST + st * 8 + (lane & 3);
                bf[ni][0] = Bh[b];
                bf[ni][1] = Bh[b + 4];
            }
            #pragma unroll
            for (int mi = 0; mi < 2; mi++)
                #pragma unroll
                for (int ni = 0; ni < 8; ni++)
                    MMA_F16(a2[mi][ni], af[mi], bf[ni]);
        }

        #pragma unroll
        for (int mi = 0; mi < 2; mi++)
            #pragma unroll
            for (int ni = 0; ni < 8; ni++) {
                int r0 = m0 + wm * 32 + mi * 16 + (lane >> 2);
                int cc = wn * 64 + ni * 8 + 2 * (lane & 3);
                int wcol = nt * 64 + (cc >> 1);
                g_qkvh[r0 * 192 + wcol]       = pack_h2(a2[mi][ni][0], a2[mi][ni][1]);
                g_qkvh[(r0 + 8) * 192 + wcol] = pack_h2(a2[mi][ni][2], a2[mi][ni][3]);
            }
        __syncthreads();
    }
}

// ---------------- Attention: fp16 qkv in, fp32 smem compute, fp16 ao out ----
__global__ void __launch_bounds__(256) attn_kernel2()
{
    extern __shared__ float qs[];          // 32 rows x stride 388 (fp32)
    const int bid = blockIdx.x;
    const int wp = bid & 15;
    const int h  = (bid >> 4) & 31;
    const int b  = bid >> 9;
    const int w0 = wp * 2;
    const int t  = threadIdx.x;

    #pragma unroll
    for (int j = 0; j < 24; j++) {
        int idx = t + j * 256;
        int ti = idx / 192, w = idx % 192;
        int s_ = ti >> 1, wl = ti & 1;
        uint32_t u = g_qkvh[(((b * 16 + s_) * 1024) + h * 32 + w0 + wl) * 192 + w];
        float2 f = unpack_h2(u);
        *(float2*)&qs[ti * 388 + 2 * w] = f;
    }
    __syncthreads();

    const int gl = t >> 4, sq = t & 15;
    const int nh = gl & 7, wl = gl >> 3;
    const int ti_q = sq * 2 + wl;
    const float* qrow = &qs[ti_q * 388 + nh * 48];
    float q[16];
    #pragma unroll
    for (int d = 0; d < 16; d++) q[d] = qrow[d];

    float sc[16];
    float mx = -1e30f;
    #pragma unroll
    for (int l = 0; l < 16; l++) {
        const float* krow = &qs[(l * 2 + wl) * 388 + nh * 48 + 16];
        float d = 0.0f;
        #pragma unroll
        for (int dd = 0; dd < 16; dd++) d += q[dd] * krow[dd];
        float m = (l <= sq) ? 1.0f : -1000.0f;
        sc[l] = d * 0.25f + m;
        mx = fmaxf(mx, sc[l]);
    }
    float sum = 0.0f;
    #pragma unroll
    for (int l = 0; l < 16; l++) { sc[l] = expf(sc[l] - mx); sum += sc[l]; }
    float inv = 1.0f / sum;

    float o[16] = {};
    #pragma unroll
    for (int l = 0; l < 16; l++) {
        float pl = sc[l] * inv;
        const float* vrow = &qs[(l * 2 + wl) * 388 + nh * 48 + 32];
        #pragma unroll
        for (int dd = 0; dd < 16; dd++) o[dd] += pl * vrow[dd];
    }
    __syncthreads();
    #pragma unroll
    for (int d = 0; d < 16; d++) qs[ti_q * 388 + nh * 16 + d] = o[d];
    __syncthreads();

    #pragma unroll
    for (int j = 0; j < 8; j++) {
        int idx = t + j * 256;
        int ti = idx >> 6, w = idx & 63;
        int s_ = ti >> 1, wl2 = ti & 1;
        g_aoh[(((b * 16 + s_) * 1024) + h * 32 + w0 + wl2) * 64 + w]
            = pack_h2(qs[ti * 388 + 2 * w], qs[ti * 388 + 2 * w + 1]);
    }
}

// ---------------- out GEMM (fp16) + residual + pack into g_padx -------------
__global__ void __launch_bounds__(256) gemm_out_pack_kernel(
    const float* __restrict__ Wout, const float* __restrict__ inputs)
{
    extern __shared__ uint32_t osm[];
    uint32_t* Ah = osm;            // 128 x AST
    uint32_t* Bh = osm + 8704;

    const int m0 = blockIdx.x * 128;
    const int t = threadIdx.x, lane = t & 31, warp = t >> 5;
    const int wm = warp & 3, wn = warp >> 2;

    #pragma unroll
    for (int i = 0; i < 8; i++) {
        int idx = t + i * 256;
        int row = idx >> 4, q4 = idx & 15;
        *(uint4*)&Ah[row * AST + q4 * 4] = *(const uint4*)&g_aoh[(m0 + row) * 64 + q4 * 4];
    }
    #pragma unroll
    for (int i = 0; i < 32; i++) {
        int idx = t + i * 256;
        int n = idx & 127, kp = idx >> 7;
        Bh[n * AST + kp] = pack_h2(Wout[(2 * kp) * 128 + n], Wout[(2 * kp + 1) * 128 + n]);
    }
    __syncthreads();

    float acc[2][8][4] = {};
    #pragma unroll
    for (int st = 0; st < 8; st++) {
        uint32_t af[2][4], bf[8][2];
        #pragma unroll
        for (int mi = 0; mi < 2; mi++) {
            int base = (wm * 32 + mi * 16 + (lane >> 2)) * AST + st * 8 + (lane & 3);
            af[mi][0] = Ah[base];
            af[mi][1] = Ah[base + 8 * AST];
            af[mi][2] = Ah[base + 4];
            af[mi][3] = Ah[base + 8 * AST + 4];
        }
        #pragma unroll
        for (int ni = 0; ni < 8; ni++) {
            int b = (wn * 64 + ni * 8 + (lane >> 2)) * AST + st * 8 + (lane & 3);
            bf[ni][0] = Bh[b];
            bf[ni][1] = Bh[b + 4];
        }
        #pragma unroll
        for (int mi = 0; mi < 2; mi++)
            #pragma unroll
            for (int ni = 0; ni < 8; ni++)
                MMA_F16(acc[mi][ni], af[mi], bf[ni]);
    }

    #pragma unroll
    for (int mi = 0; mi < 2; mi++)
        #pragma unroll
        for (int ni = 0; ni < 8; ni++) {
            int cc = wn * 64 + ni * 8 + 2 * (lane & 3);     // even e
            int chunk = cc >> 4, jp = (cc & 15) >> 1;
            #pragma unroll
            for (int half = 0; half < 2; half++) {
                int r = m0 + wm * 32 + mi * 16 + (lane >> 2) + half * 8;
                float2 rv = *(const float2*)&inputs[r * 128 + cc];
                float vx = acc[mi][ni][half * 2 + 0] + rv.x;
                float vy = acc[mi][ni][half * 2 + 1] + rv.y;
                int b_ = r >> 14, s_ = (r >> 10) & 15, y = (r >> 5) & 31, x = r & 31;
                g_padx[(s_ * 8 + b_) * SBW + (chunk * 8 + jp) * JPL + (y + 1) * 36 + (x + 1)]
                    = pack_h2(vx, vy);
            }
        }
}

// ---------------- init: zero c + padh buf0 + weight prepack, ONE launch -----
// idx domain 1,675,264 = NPIX*EE (c) + BB*SBW (padh buf0); first 589,824 idx
// additionally pack one weight word each.
__global__ void init_kernel(const float* __restrict__ convk)
{
    int idx = blockIdx.x * 256 + threadIdx.x;
    if (idx < NPIX * EE) g_c[idx] = 0.0f;
    else                 g_padh[idx - NPIX * EE] = 0u;

    if (idx < 16 * 9 * 8 * 512) {
        int ocp = idx & 511;
        int t2 = idx >> 9;
        int j  = t2 & 7;
        int t3 = t2 >> 3;
        int tap = t3 % 9;
        int chunk = t3 / 9;
        int eg   = ocp >> 7;
        int gate = (ocp >> 5) & 3;
        int el   = ocp & 31;
        int oc   = gate * 128 + eg * 32 + el;
        int ic0  = chunk * 16 + 2 * j;
        g_w2h[idx] = pack_h2(convk[(oc * 256 + ic0) * 9 + tap],
                             convk[(oc * 256 + ic0 + 1) * 9 + tap]);
    }
}

// ---------------- fused conv + LSTM gates (R14 version, proven) -------------
__global__ void __launch_bounds__(256) conv_fused_kernel(int s, float* __restrict__ out)
{
    extern __shared__ uint32_t sh[];
    uint32_t* in_base = sh;                 // 2 x 1728
    uint32_t* w_base  = sh + 2 * 1728;      // 2 x 9792
    float*    Cs      = (float*)sh;         // epilogue alias: 128 x 132

    const int b   = blockIdx.z;
    const int y0  = blockIdx.y * 4;
    const int eg  = blockIdx.x;             // oc' block = eg*128
    const int t    = threadIdx.x;
    const int lane = t & 31;
    const int warp = t >> 5;
    const int wm = warp & 3, wn = warp >> 2;
    const int jl = lane & 3, nl = lane >> 2;

    const uint32_t* padx_b = g_padx + (s * 8 + b) * SBW;
    const uint32_t* padh_r = g_padh + (s & 1) * (BB * SBW) + b * SBW;
    uint32_t*       padh_w = g_padh + ((s + 1) & 1) * (BB * SBW);
    const uint32_t sm_in = sm_u32(in_base);
    const uint32_t sm_w  = sm_u32(w_base);

    auto load_chunk = [&](int stage, int c) {
        const uint32_t* ibase = (c < 8) ? (padx_b + c * CHW) : (padh_r + (c - 8) * CHW);
        uint32_t id = sm_in + (uint32_t)stage * 1728u * 4u;
        #pragma unroll
        for (int k = 0; k < 2; k++) {
            int idx = t + k * 256;
            if (idx < 432) {
                int j = idx / 54, rem = idx % 54;
                int r = rem / 9, c16 = rem % 9;
                cpa16(id + (uint32_t)(j * 216 + r * 36 + c16 * 4) * 4u,
                      ibase + j * JPL + (y0 + r) * 36 + c16 * 4);
            }
        }
        uint32_t wd = sm_w + (uint32_t)stage * 9792u * 4u;
        const uint32_t* wbase = g_w2h + c * 36864 + eg * 128;
        #pragma unroll
        for (int k = 0; k < 9; k++) {
            int idx = t + k * 256;
            int row = idx >> 5, c16 = idx & 31;
            cpa16(wd + (uint32_t)(row * 136 + c16 * 4) * 4u,
                  wbase + row * 512 + c16 * 4);
        }
        asm volatile("cp.async.commit_group;\n");
    };

    float acc[2][8][4] = {};
    load_chunk(0, 0);

    for (int c = 0; c < 16; c++) {
        const int stage = c & 1;
        if (c < 15) {
            load_chunk(stage ^ 1, c + 1);
            asm volatile("cp.async.wait_group 1;\n");
        } else {
            asm volatile("cp.async.wait_group 0;\n");
        }
        __syncthreads();

        const uint32_t* in_s = in_base + stage * 1728;
        const uint32_t* w_s  = w_base  + stage * 9792;

        #pragma unroll
        for (int tp = 0; tp < 9; tp++) {
            const int ky = tp / 3, kx = tp % 3;
            uint32_t bf[8][2];
            #pragma unroll
            for (int g = 0; g < 8; g++) {
                int ocl = wn * 64 + g * 8 + nl;
                bf[g][0] = w_s[(tp * 8 + jl    ) * 136 + ocl];
                bf[g][1] = w_s[(tp * 8 + jl + 4) * 136 + ocl];
            }
            const int rr = wm + ky;
            #pragma unroll
            for (int f = 0; f < 2; f++) {
                int col = f * 16 + nl + kx;
                const uint32_t* p0 = in_s + jl * 216 + rr * 36 + col;
                const uint32_t* p1 = in_s + (jl + 4) * 216 + rr * 36 + col;
                uint32_t a0 = p0[0], a1 = p0[8], a2 = p1[0], a3 = p1[8];
                #pragma unroll
                for (int g = 0; g < 8; g++) {
                    asm volatile(
                        "mma.sync.aligned.m16n8k16.row.col.f32.f16.f16.f32 "
                        "{%0,%1,%2,%3}, {%4,%5,%6,%7}, {%8,%9}, {%0,%1,%2,%3};"
                        : "+f"(acc[f][g][0]), "+f"(acc[f][g][1]),
                          "+f"(acc[f][g][2]), "+f"(acc[f][g][3])
                        : "r"(a0), "r"(a1), "r"(a2), "r"(a3),
                          "r"(bf[g][0]), "r"(bf[g][1]));
                }
            }
        }
        __syncthreads();
    }

    // ---- epilogue: stage C tile in smem (aliases pipeline buffers) ----
    #pragma unroll
    for (int f = 0; f < 2; f++) {
        #pragma unroll
        for (int g = 0; g < 8; g++) {
            int mloc = wm * 32 + f * 16 + nl;
            int ocl  = wn * 64 + g * 8 + 2 * (lane & 3);
            *(float2*)&Cs[mloc * 132 + ocl]       = make_float2(acc[f][g][0], acc[f][g][1]);
            *(float2*)&Cs[(mloc + 8) * 132 + ocl] = make_float2(acc[f][g][2], acc[f][g][3]);
        }
    }
    __syncthreads();

    // ---- gates: each thread handles 16 (px, el) quads ----
    __half* padh_h = (__half*)padh_w;
    #pragma unroll
    for (int i = 0; i < 16; i++) {
        int q  = i * 256 + t;
        int el = q & 31, px = q >> 5;
        int row = px >> 5, x = px & 31;
        int y = y0 + row;
        float ci = Cs[px * 132 + el];
        float cf = Cs[px * 132 + 32 + el];
        float co = Cs[px * 132 + 64 + el];
        float cg = Cs[px * 132 + 96 + el];
        int e  = eg * 32 + el;
        int pb = b * 1024 + y * 32 + x;
        float c  = g_c[pb * 128 + e];
        float si = 1.0f / (1.0f + expf(-ci));
        float sf = 1.0f / (1.0f + expf(-cf));
        float so = 1.0f / (1.0f + expf(-co));
        float cn = sf * c + si * tanhf(cg);
        float hn = so * tanhf(cn);
        g_c[pb * 128 + e] = cn;
        out[((b * 16 + s) * 1024 + y * 32 + x) * 128 + e] = hn;
        int chunk_h = e >> 4, j = (e & 15) >> 1, pos = e & 1;
        padh_h[((((b * 8 + chunk_h) * CHW) + j * JPL + (y + 1) * 36 + (x + 1)) << 1) | pos]
            = __float2half_rn(hn);
    }
}

// ---------------- launch ----------------------------------------------------
extern "C" void kernel_launch(void* const* d_in, const int* in_sizes, int n_in,
                              void* d_out, int out_size)
{
    const float* inputs = (const float*)d_in[0];
    const float* W_proj = (const float*)d_in[1];
    const float* gamma  = (const float*)d_in[2];
    const float* beta   = (const float*)d_in[3];
    const float* W_in   = (const float*)d_in[4];
    const float* W_out  = (const float*)d_in[5];
    const float* convk  = (const float*)d_in[6];
    float* out = (float*)d_out;

    const int FRONT_SMEM = 17408 * 4;                 // 69632 -> 3 blocks/SM
    const int OUT_SMEM   = 17408 * 4;                 // 69632
    const int ATTN_SMEM  = 32 * 388 * 4;              // 49664
    const int CONV_SMEM  = (2 * 1728 + 2 * 9792) * 4; // 92160
    cudaFuncSetAttribute(front_fused_kernel, cudaFuncAttributeMaxDynamicSharedMemorySize, FRONT_SMEM);
    cudaFuncSetAttribute(gemm_out_pack_kernel, cudaFuncAttributeMaxDynamicSharedMemorySize, OUT_SMEM);
    cudaFuncSetAttribute(attn_kernel2, cudaFuncAttributeMaxDynamicSharedMemorySize, ATTN_SMEM);
    cudaFuncSetAttribute(conv_fused_kernel, cudaFuncAttributeMaxDynamicSharedMemorySize, CONV_SMEM);

    // 0) init: zero c + padh buf0 + weight prepack (no deps, one launch)
    init_kernel<<<(NPIX * EE + BB * SBW) / 256, 256>>>(convk);
    // 1) fused: silu(inputs@W_proj) -> LN -> @W_in -> g_qkvh (fp16)
    front_fused_kernel<<<NTOK / 128, 256, FRONT_SMEM>>>(inputs, W_proj, W_in, gamma, beta);
    // 2) attention (fp16 in/out, fp32 compute)
    attn_kernel2<<<BB * HH * (WW / 2), 256, ATTN_SMEM>>>();
    // 3) out GEMM + residual, packed straight into g_padx
    gemm_out_pack_kernel<<<NTOK / 128, 256, OUT_SMEM>>>(W_out, inputs);
    // 4) ConvLSTM scan: one fused kernel per step, ping-pong h buffers
    for (int s = 0; s < SS; s++) {
        conv_fused_kernel<<<dim3(4, 8, 8), 256, CONV_SMEM>>>(s, out);
    }
}